// round 15
// baseline (speedup 1.0000x reference)
#include <cuda_runtime.h>
#include <cuda_fp16.h>
#include <cstdint>
#include <math.h>

// ---- problem constants ----
#define N_IMG 5
#define C_CH  256
#define HH    128
#define WWID  128
#define HW    16384
#define NP    81920            // N_IMG * HW
#define C4    1024             // 4*C
#define C2    512              // 2*C
#define THRE  0.01f
#define NCHW_TOT (N_IMG * C_CH * HW)

// output layout: [sparse_feature | loss | rate | sparse_mask]
#define LOSS_IDX 20971520
#define RATE_IDX 20971521
#define SM_OFF   20971522

// gaussian weights
#define G2_C 0.15915494309189535f
#define G2_E 0.09653235263005391f
#define G2_D 0.05855018091964769f
#define G1_C 0.45186276187760605f
#define G1_S 0.27406861906119697f

// ---- device scratch ----
__device__ __align__(16) __half g_Uh[(size_t)NP * C4];   // fp16(U + b1), [p][j]
__device__ __align__(16) __half g_Vh[(size_t)NP * C4];   // fp16(V),      [p][j]
__device__ __align__(16) __half g_ZT[(size_t)NP * C4];   // relu(Uh+Vh)
__device__ __align__(16) __half g_ZP[(size_t)NP * C4];   // relu(Uh_roll+Vh)
__device__ __align__(16) __half g_Fh[(size_t)NCHW_TOT];  // fp16 feat [n][c][p]
__device__ __align__(16) __half g_Sh[(size_t)NCHW_TOT];  // fp16 sparse [n][c][p]
__device__ __align__(16) __half g_W2h[(size_t)C4 * C4];
__device__ __align__(16) __half g_W1h[(size_t)C4 * C2];
__device__ float g_avg[N_IMG * C_CH];
__device__ float g_mx[N_IMG * C_CH];
__device__ float g_chcoef[4 * C_CH];
__device__ float g_cmean[NP];
__device__ float g_cmax[NP];
__device__ float g_spatt[NP];
__device__ float g_act[NP];
__device__ float g_spcoef[4 * HW];
__device__ float g_tT[NP];
__device__ float g_tP[NP];
__device__ unsigned long long g_cnt;
__device__ double g_lossAcc;

__device__ __forceinline__ float sigmoidf(float x) { return 1.f / (1.f + expf(-x)); }
__device__ __forceinline__ float softplusf(float x) { return fmaxf(x, 0.f) + log1pf(expf(-fabsf(x))); }
__device__ __forceinline__ float g2w(int ky, int kx) {
    int d = (ky != 1) + (kx != 1);
    return d == 0 ? G2_C : (d == 1 ? G2_E : G2_D);
}

// ================= mma.sync helpers =================
__device__ __forceinline__ uint32_t smem_u32(const void* p) {
    uint32_t a;
    asm("{ .reg .u64 t; cvta.to.shared.u64 t, %1; cvt.u32.u64 %0, t; }" : "=r"(a) : "l"(p));
    return a;
}
__device__ __forceinline__ void ldsm4(uint32_t& r0, uint32_t& r1, uint32_t& r2, uint32_t& r3, uint32_t a) {
    asm volatile("ldmatrix.sync.aligned.m8n8.x4.shared.b16 {%0,%1,%2,%3}, [%4];"
                 : "=r"(r0), "=r"(r1), "=r"(r2), "=r"(r3) : "r"(a));
}
__device__ __forceinline__ void ldsm4t(uint32_t& r0, uint32_t& r1, uint32_t& r2, uint32_t& r3, uint32_t a) {
    asm volatile("ldmatrix.sync.aligned.m8n8.x4.trans.shared.b16 {%0,%1,%2,%3}, [%4];"
                 : "=r"(r0), "=r"(r1), "=r"(r2), "=r"(r3) : "r"(a));
}
__device__ __forceinline__ void mma_f16(float* c, uint32_t a0, uint32_t a1, uint32_t a2, uint32_t a3,
                                        uint32_t b0, uint32_t b1) {
    asm volatile("mma.sync.aligned.m16n8k16.row.col.f32.f16.f16.f32 "
                 "{%0,%1,%2,%3}, {%4,%5,%6,%7}, {%8,%9}, {%0,%1,%2,%3};"
                 : "+f"(c[0]), "+f"(c[1]), "+f"(c[2]), "+f"(c[3])
                 : "r"(a0), "r"(a1), "r"(a2), "r"(a3), "r"(b0), "r"(b1));
}
__device__ __forceinline__ uint32_t pack2h(float a, float b) {
    __half ha = __float2half_rn(a);
    __half hb = __float2half_rn(b);
    return (uint32_t)__half_as_ushort(ha) | ((uint32_t)__half_as_ushort(hb) << 16);
}
// z = relu(u + v) on packed fp16x2
__device__ __forceinline__ uint32_t hrelu_add2(uint32_t u, uint32_t v) {
    __half2 s = __hadd2(*(__half2*)&u, *(__half2*)&v);
    s = __hmax2(s, __float2half2_rn(0.f));
    return *(uint32_t*)&s;
}

// ------------------------------------------------------------------
// prep: zero accumulators + convert W1, W2 to fp16 (one launch)
__global__ void prep_kernel(const float* __restrict__ W1, const float* __restrict__ W2) {
    int i = blockIdx.x * blockDim.x + threadIdx.x;
    if (i == 0) { g_cnt = 0ULL; g_lossAcc = 0.0; }
    if (i < NP) { g_tT[i] = 0.f; g_tP[i] = 0.f; }
    if (i < C4 * C4) g_W2h[i] = __float2half_rn(W2[i]);
    if (i < C4 * C2) g_W1h[i] = __float2half_rn(W1[i]);
}

__global__ void reduce_nc_kernel(const float* __restrict__ feat) {
    int nc = blockIdx.x;
    const float* base = feat + (size_t)nc * HW;
    int t = threadIdx.x;
    float s = 0.f, m = -3.402823466e38f;
    for (int i = t; i < HW; i += 256) { float v = base[i]; s += v; m = fmaxf(m, v); }
    __shared__ float ss[256], sm[256];
    ss[t] = s; sm[t] = m;
    __syncthreads();
    for (int st = 128; st > 0; st >>= 1) {
        if (t < st) { ss[t] += ss[t + st]; sm[t] = fmaxf(sm[t], sm[t + st]); }
        __syncthreads();
    }
    if (t == 0) { g_avg[nc] = ss[0] * (1.f / HW); g_mx[nc] = sm[0]; }
}

__global__ void reduce_pix_kernel(const float* __restrict__ feat) {
    int p = blockIdx.x * blockDim.x + threadIdx.x;
    if (p >= NP) return;
    int n = p >> 14, pix = p & 16383;
    const float* base = feat + (size_t)n * C_CH * HW + pix;
    float s = 0.f, m = -3.402823466e38f;
    #pragma unroll 8
    for (int c = 0; c < C_CH; c++) { float v = base[(size_t)c * HW]; s += v; m = fmaxf(m, v); }
    g_cmean[p] = s * (1.f / C_CH);
    g_cmax[p] = m;
}

// ------------------------------------------------------------------
// ch_coef, parallel: grid = 4 n * 8 c-tiles; hidden layer recomputed per block (tiny)
__global__ void chcoef_kernel(const float* __restrict__ w1, const float* __restrict__ w2,
                              const float* __restrict__ cfw) {
    __shared__ float hsS[N_IMG * 16];
    __shared__ float ego[C_CH];
    __shared__ float att[C_CH];
    __shared__ float tmp[34];
    int t = threadIdx.x;
    int n = blockIdx.x >> 3;          // 0..3
    int cb = blockIdx.x & 7;          // c-tile, 32 c's
    if (t < N_IMG * 16) {
        int nn = t / 16, h = t % 16;
        const float* wr = w1 + h * C_CH;
        const float* av = g_avg + nn * C_CH;
        const float* mv = g_mx + nn * C_CH;
        float sa = 0.f, sm = 0.f;
        for (int c = 0; c < C_CH; c++) { sa += av[c] * wr[c]; sm += mv[c] * wr[c]; }
        hsS[t] = fmaxf(sa, 0.f) + fmaxf(sm, 0.f);
    }
    __syncthreads();
    // ego / att rows (each thread one k)
    {
        float p0 = 0.f, p1 = 0.f;
        const float* w2r = w2 + t * 16;
        #pragma unroll
        for (int h = 0; h < 16; h++) {
            float w = w2r[h];
            p0 += hsS[h] * w;                   // n=0
            p1 += hsS[(n + 1) * 16 + h] * w;    // n+1
        }
        ego[t] = 1.f - sigmoidf(p0);
        att[t] = sigmoidf(p1);
    }
    __syncthreads();
    // 34 halo dots: c = cb*32 - 1 + j, warp per j
    int wid = t >> 5, lane = t & 31;
    for (int j = wid; j < 34; j += 8) {
        int c = cb * 32 - 1 + j;
        if (c < 0 || c > 255) { if (lane == 0) tmp[j] = 0.f; continue; }
        const float* row = cfw + (size_t)c * C2;
        float p = 0.f;
        for (int k = lane; k < C_CH; k += 32)
            p += ego[k] * row[k] + att[k] * row[C_CH + k];
        #pragma unroll
        for (int o = 16; o > 0; o >>= 1) p += __shfl_xor_sync(0xFFFFFFFFu, p, o);
        if (lane == 0) tmp[j] = sigmoidf(p);
    }
    __syncthreads();
    if (t < 32) {
        int c = cb * 32 + t;
        float v = G1_C * tmp[t + 1];
        if (c > 0)   v += G1_S * tmp[t];
        if (c < 255) v += G1_S * tmp[t + 2];
        g_chcoef[n * C_CH + c] = v;
    }
}

__global__ void spatial_kernel(const float* __restrict__ sw) {
    int idx = blockIdx.x * blockDim.x + threadIdx.x;
    if (idx >= NP) return;
    int n = idx >> 14, pix = idx & 16383;
    int h = pix >> 7, w = pix & 127;
    float satt = 0.f, act = 0.f;
    #pragma unroll
    for (int ky = 0; ky < 3; ky++) {
        int hh = h + ky - 1;
        if (hh < 0 || hh >= HH) continue;
        #pragma unroll
        for (int kx = 0; kx < 3; kx++) {
            int ww = w + kx - 1;
            if (ww < 0 || ww >= WWID) continue;
            int q = n * HW + hh * WWID + ww;
            float cm = g_cmean[q], cx = g_cmax[q];
            satt += cm * sw[ky * 3 + kx] + cx * sw[9 + ky * 3 + kx];
            act += g2w(ky, kx) * sigmoidf(cm);
        }
    }
    g_spatt[idx] = sigmoidf(satt);
    g_act[idx] = act;
}

__global__ void spcoef_kernel(const float* __restrict__ spfus) {
    int idx = blockIdx.x * blockDim.x + threadIdx.x;
    if (idx >= 4 * HW) return;
    int m = idx >> 14, pix = idx & 16383;
    int h = pix >> 7, w = pix & 127;
    float wa = spfus[0], wb = spfus[1];
    float acc = 0.f;
    #pragma unroll
    for (int ky = 0; ky < 3; ky++) {
        int hh = h + ky - 1;
        if (hh < 0 || hh >= HH) continue;
        #pragma unroll
        for (int kx = 0; kx < 3; kx++) {
            int ww = w + kx - 1;
            if (ww < 0 || ww >= WWID) continue;
            int q = hh * WWID + ww;
            float pre = wa * (1.f - g_spatt[q]) + wb * g_spatt[(m + 1) * HW + q];
            acc += g2w(ky, kx) * sigmoidf(pre);
        }
    }
    g_spcoef[idx] = acc;
}

// mask + sparse_feature + sparse_mask + fp16 copies of feat & sparse (fused)
__global__ void mask_kernel(const float* __restrict__ feat,
                            float* __restrict__ out_sf, float* __restrict__ out_sm) {
    int t = threadIdx.x;
    unsigned int cnt = 0;
    for (int i2 = blockIdx.x * blockDim.x + t; i2 < NCHW_TOT / 2; i2 += gridDim.x * blockDim.x) {
        int idx = i2 * 2;
        int n = idx / (C_CH * HW);
        float2 f = *(const float2*)(feat + idx);
        float2 sf, sm;
        if (n == 0) { sf = f; sm = make_float2(1.f, 1.f); }
        else {
            int rem = idx - n * C_CH * HW;
            int c = rem >> 14, p = rem & 16383;
            int m = n - 1;
            float cc = g_chcoef[m * C_CH + c];
            float v0 = cc * g_spcoef[m * HW + p] * g_act[n * HW + p];
            float v1 = cc * g_spcoef[m * HW + p + 1] * g_act[n * HW + p + 1];
            bool mk0 = v0 > THRE, mk1 = v1 > THRE;
            sf.x = mk0 ? f.x : 0.f; sm.x = mk0 ? 1.f : 0.f;
            sf.y = mk1 ? f.y : 0.f; sm.y = mk1 ? 1.f : 0.f;
            cnt += (mk0 ? 1u : 0u) + (mk1 ? 1u : 0u);
        }
        *(float2*)(out_sf + idx) = sf;
        *(float2*)(out_sm + idx) = sm;
        *(uint32_t*)&g_Fh[idx] = pack2h(f.x, f.y);
        *(uint32_t*)&g_Sh[idx] = pack2h(sf.x, sf.y);
    }
    __shared__ unsigned int sc[256];
    sc[t] = cnt;
    __syncthreads();
    for (int s = 128; s > 0; s >>= 1) { if (t < s) sc[t] += sc[t + s]; __syncthreads(); }
    if (t == 0) atomicAdd(&g_cnt, (unsigned long long)sc[0]);
}

// ------------------------------------------------------------------
// z = relu(Uh[roll]+Vh) for both rolls; each thread owns one (pix,k8) column
// across all 5 images so Uh/Vh are read exactly once.
__global__ void zprep_kernel() {
    int i = blockIdx.x * blockDim.x + threadIdx.x;   // 0 .. 16384*128-1
    if (i >= HW * (C4 / 8)) return;
    int pix = i >> 7;
    int k = (i & 127) * 8;
    uint4 u[N_IMG], v[N_IMG];
    #pragma unroll
    for (int n = 0; n < N_IMG; n++) {
        size_t e = ((((size_t)n << 14) | pix) << 10) | k;
        u[n] = *(const uint4*)(g_Uh + e);
        v[n] = *(const uint4*)(g_Vh + e);
    }
    #pragma unroll
    for (int n = 0; n < N_IMG; n++) {
        int nr = (n + 1 == N_IMG) ? 0 : n + 1;
        size_t e = ((((size_t)n << 14) | pix) << 10) | k;
        uint4 zt, zp;
        zt.x = hrelu_add2(u[n].x, v[n].x);  zp.x = hrelu_add2(u[nr].x, v[n].x);
        zt.y = hrelu_add2(u[n].y, v[n].y);  zp.y = hrelu_add2(u[nr].y, v[n].y);
        zt.z = hrelu_add2(u[n].z, v[n].z);  zp.z = hrelu_add2(u[nr].z, v[n].z);
        zt.w = hrelu_add2(u[n].w, v[n].w);  zp.w = hrelu_add2(u[nr].w, v[n].w);
        *(uint4*)(g_ZT + e) = zt;
        *(uint4*)(g_ZP + e) = zp;
    }
}

// ==================================================================
// GEMM1 (mma.sync fp16, A-resident, smem-staged epilogue):
// Uh[p][j] = fp16(sum_c A*W1a + b1), Vh = fp16(sum_c A*W1b)
// Block per (P0, which); A tile [k=256][m=128] resident in smem (272B rows);
// jt loop streams W1 tiles (double-buffered [n=128][k=32] rows 80B).
// Epilogue stages each 64x128 half-tile through the W region (272B-pad rows)
// for fully-coalesced 16B global stores.
#define G1_A_OF 0
#define G1_W_OF 69632
#define G1_W_STAGE 10240
#define G1_SMEM (69632 + 2 * 10240)
__global__ __launch_bounds__(256, 2) void gemm1_mma(const float* __restrict__ b1) {
    extern __shared__ __align__(16) char sm1[];
    const int tid = threadIdx.x;
    const int wid = tid >> 5, lane = tid & 31;
    const int wm = wid & 3, wn = wid >> 2;
    const int g = lane >> 2, t2 = (lane & 3) * 2;
    const size_t P0 = (size_t)blockIdx.x * 128;
    const int which = blockIdx.y;              // 0: U from feat, 1: V from sparse
    const int n = (int)(P0 >> 14), pl = (int)(P0 & 16383);
    const __half* Ah = (which ? g_Sh : g_Fh) + (size_t)n * C_CH * HW + pl;
    __half* Out = which ? g_Vh : g_Uh;
    const uint32_t sb = smem_u32(sm1);

    // load full A tile resident: 256 k-rows x 128 m, 272B rows
    #pragma unroll
    for (int i = 0; i < 16; i++) {
        int s = tid + 256 * i;
        int r = s >> 4, q = s & 15;
        uint4 v = *(const uint4*)(Ah + (size_t)r * HW + q * 8);
        *(uint4*)(sm1 + G1_A_OF + r * 272 + q * 16) = v;
    }

    for (int jt = 0; jt < 8; jt++) {
        const __half* Bh = g_W1h + (size_t)jt * 128 * C2 + (which ? 256 : 0);
        float acc[2][8][4];
        #pragma unroll
        for (int a = 0; a < 2; a++)
            #pragma unroll
            for (int b = 0; b < 8; b++)
                #pragma unroll
                for (int c = 0; c < 4; c++) acc[a][b][c] = 0.f;

        uint4 pw[2];
        // W stage 0
        #pragma unroll
        for (int i = 0; i < 2; i++) {
            int s = tid + 256 * i;
            int o = s >> 2, qq = s & 3;
            pw[i] = *(const uint4*)(Bh + (size_t)o * C2 + qq * 8);
        }
        #pragma unroll
        for (int i = 0; i < 2; i++) {
            int s = tid + 256 * i;
            int o = s >> 2, qq = s & 3;
            *(uint4*)(sm1 + G1_W_OF + o * 80 + qq * 16) = pw[i];
        }
        __syncthreads();   // A (jt=0) + W stage resident; also guards W buf reuse across jt

        for (int kc = 0; kc < 8; kc++) {
            if (kc + 1 < 8) {
                int k0 = (kc + 1) * 32;
                #pragma unroll
                for (int i = 0; i < 2; i++) {
                    int s = tid + 256 * i;
                    int o = s >> 2, qq = s & 3;
                    pw[i] = *(const uint4*)(Bh + (size_t)o * C2 + k0 + qq * 8);
                }
            }
            const uint32_t wbase = sb + G1_W_OF + (kc & 1) * G1_W_STAGE;
            #pragma unroll
            for (int ks = 0; ks < 2; ks++) {
                uint32_t bh[8][2];
                #pragma unroll
                for (int np = 0; np < 4; np++) {
                    int row = wn * 64 + np * 16 + (lane & 7) + ((lane >> 4) & 1) * 8;
                    uint32_t col = ks * 32 + ((lane >> 3) & 1) * 16;
                    uint32_t a = wbase + row * 80 + col;
                    ldsm4(bh[2 * np][0], bh[2 * np][1], bh[2 * np + 1][0], bh[2 * np + 1][1], a);
                }
                #pragma unroll
                for (int mf = 0; mf < 2; mf++) {
                    int rowk = kc * 32 + ks * 16 + ((lane >> 4) & 1) * 8 + (lane & 7);
                    uint32_t col = (wm * 32 + mf * 16 + ((lane >> 3) & 1) * 8) * 2;
                    uint32_t a = sb + G1_A_OF + rowk * 272 + col;
                    uint32_t a0, a1, a2, a3;
                    ldsm4t(a0, a1, a2, a3, a);
                    #pragma unroll
                    for (int nf = 0; nf < 8; nf++)
                        mma_f16(acc[mf][nf], a0, a1, a2, a3, bh[nf][0], bh[nf][1]);
                }
            }
            if (kc + 1 < 8) {
                char* buf = sm1 + G1_W_OF + ((kc + 1) & 1) * G1_W_STAGE;
                #pragma unroll
                for (int i = 0; i < 2; i++) {
                    int s = tid + 256 * i;
                    int o = s >> 2, qq = s & 3;
                    *(uint4*)(buf + o * 80 + qq * 16) = pw[i];
                }
            }
            __syncthreads();
        }

        // -------- staged epilogue: two 64x128 half-tiles through W region --------
        // smem rows padded to 272B (conflict-free); slot_row = wm*16 + (g|g+8)
        #pragma unroll
        for (int mf = 0; mf < 2; mf++) {
            char* ep = sm1 + G1_W_OF;
            #pragma unroll
            for (int nf = 0; nf < 8; nf++) {
                int col = wn * 64 + nf * 8 + t2;   // 0..127 within jt tile
                int s0 = wm * 16 + g;
                float ba = 0.f, bb = 0.f;
                if (which == 0) {
                    int gc = jt * 128 + col;
                    ba = __ldg(b1 + gc); bb = __ldg(b1 + gc + 1);
                }
                *(uint32_t*)(ep + s0 * 272 + col * 2) = pack2h(acc[mf][nf][0] + ba, acc[mf][nf][1] + bb);
                *(uint32_t*)(ep + (s0 + 8) * 272 + col * 2) = pack2h(acc[mf][nf][2] + ba, acc[mf][nf][3] + bb);
            }
            __syncthreads();
            // coalesced store: thread t -> slot s = t>>2, 64B segment (t&3)
            {
                int s = tid >> 2, seg = tid & 3;
                int wmp = s >> 4, idx = s & 15;
                size_t gr = P0 + wmp * 32 + mf * 16 + idx;
                __half* dst = Out + gr * C4 + jt * 128 + seg * 32;
                const char* src = ep + s * 272 + seg * 64;
                #pragma unroll
                for (int q = 0; q < 4; q++)
                    *(uint4*)(dst + q * 8) = *(const uint4*)(src + q * 16);
            }
            __syncthreads();
        }
    }
}

// ==================================================================
// GEMM2 (mma.sync fp16, o-split for tail smoothing):
// grid (NP/128, 2 rolls, 2 o-halves); each block does 4 o-tiles and
// atomicAdds its partial T into g_tT/g_tP (exactly 2 contributors/pixel -> deterministic).
#define G2_A_OF 0
#define G2_B_OF 10240
#define G2_STAGE 20480
__global__ __launch_bounds__(256, 2) void gemm2_mma(const float* __restrict__ b2,
                                                    const float* __restrict__ w3) {
    extern __shared__ __align__(16) char sm2[];
    const int tid = threadIdx.x;
    const int wid = tid >> 5, lane = tid & 31;
    const int wm = wid & 3, wn = wid >> 2;
    const int g = lane >> 2, t2 = (lane & 3) * 2;
    const size_t P0 = (size_t)blockIdx.x * 128;
    const int roll = blockIdx.y;
    const int oh = blockIdx.z;                 // o-half: nt in [oh*4, oh*4+4)
    const __half* Z = (roll ? g_ZP : g_ZT) + P0 * C4;
    float* tOut = roll ? g_tP : g_tT;
    const uint32_t sb = smem_u32(sm2);

    float sAcc[4] = {0.f, 0.f, 0.f, 0.f};

    for (int nt = oh * 4; nt < oh * 4 + 4; nt++) {
        const int o0 = nt * 128;
        const __half* Wh = g_W2h + (size_t)o0 * C4;
        float acc[2][8][4];
        #pragma unroll
        for (int a = 0; a < 2; a++)
            #pragma unroll
            for (int b = 0; b < 8; b++)
                #pragma unroll
                for (int c = 0; c < 4; c++) acc[a][b][c] = 0.f;

        uint4 pa[2], pw[2];
        {
            #pragma unroll
            for (int i = 0; i < 2; i++) {
                int s = tid + 256 * i;
                int p = s >> 2, q = s & 3;
                pa[i] = *(const uint4*)(Z + (size_t)p * C4 + q * 8);
                pw[i] = *(const uint4*)(Wh + (size_t)p * C4 + q * 8);
            }
            char* buf = sm2;
            #pragma unroll
            for (int i = 0; i < 2; i++) {
                int s = tid + 256 * i;
                int p = s >> 2, q = s & 3;
                *(uint4*)(buf + G2_A_OF + p * 80 + q * 16) = pa[i];
                *(uint4*)(buf + G2_B_OF + p * 80 + q * 16) = pw[i];
            }
        }
        __syncthreads();

        for (int kc = 0; kc < 32; kc++) {
            if (kc + 1 < 32) {
                int k0 = (kc + 1) * 32;
                #pragma unroll
                for (int i = 0; i < 2; i++) {
                    int s = tid + 256 * i;
                    int p = s >> 2, q = s & 3;
                    pa[i] = *(const uint4*)(Z + (size_t)p * C4 + k0 + q * 8);
                    pw[i] = *(const uint4*)(Wh + (size_t)p * C4 + k0 + q * 8);
                }
            }
            const uint32_t base = sb + (kc & 1) * G2_STAGE;
            #pragma unroll
            for (int ks = 0; ks < 2; ks++) {
                uint32_t bh[8][2];
                #pragma unroll
                for (int np = 0; np < 4; np++) {
                    int row = wn * 64 + np * 16 + (lane & 7) + ((lane >> 4) & 1) * 8;
                    uint32_t col = ks * 32 + ((lane >> 3) & 1) * 16;
                    uint32_t a = base + G2_B_OF + row * 80 + col;
                    ldsm4(bh[2 * np][0], bh[2 * np][1], bh[2 * np + 1][0], bh[2 * np + 1][1], a);
                }
                #pragma unroll
                for (int mf = 0; mf < 2; mf++) {
                    int row = wm * 32 + mf * 16 + (lane & 7) + ((lane >> 3) & 1) * 8;
                    uint32_t col = ks * 32 + ((lane >> 4) & 1) * 16;
                    uint32_t a = base + G2_A_OF + row * 80 + col;
                    uint32_t a0, a1, a2, a3;
                    ldsm4(a0, a1, a2, a3, a);
                    #pragma unroll
                    for (int nf = 0; nf < 8; nf++)
                        mma_f16(acc[mf][nf], a0, a1, a2, a3, bh[nf][0], bh[nf][1]);
                }
            }
            if (kc + 1 < 32) {
                char* buf = sm2 + ((kc + 1) & 1) * G2_STAGE;
                #pragma unroll
                for (int i = 0; i < 2; i++) {
                    int s = tid + 256 * i;
                    int p = s >> 2, q = s & 3;
                    *(uint4*)(buf + G2_A_OF + p * 80 + q * 16) = pa[i];
                    *(uint4*)(buf + G2_B_OF + p * 80 + q * 16) = pw[i];
                }
            }
            __syncthreads();
        }

        // fold this o-tile into per-pixel scalars
        #pragma unroll
        for (int mf = 0; mf < 2; mf++) {
            #pragma unroll
            for (int nf = 0; nf < 8; nf++) {
                int c0 = o0 + wn * 64 + nf * 8 + t2;
                float b2a = __ldg(b2 + c0), b2b = __ldg(b2 + c0 + 1);
                float w3a = __ldg(w3 + c0), w3b = __ldg(w3 + c0 + 1);
                sAcc[mf * 2 + 0] += fmaxf(acc[mf][nf][0] + b2a, 0.f) * w3a
                                  + fmaxf(acc[mf][nf][1] + b2b, 0.f) * w3b;
                sAcc[mf * 2 + 1] += fmaxf(acc[mf][nf][2] + b2a, 0.f) * w3a
                                  + fmaxf(acc[mf][nf][3] + b2b, 0.f) * w3b;
            }
        }
    }

    // reduce across the 4-lane groups (same rows, different cols)
    #pragma unroll
    for (int i = 0; i < 4; i++) {
        sAcc[i] += __shfl_xor_sync(0xFFFFFFFFu, sAcc[i], 1);
        sAcc[i] += __shfl_xor_sync(0xFFFFFFFFu, sAcc[i], 2);
    }
    __syncthreads();
    float* sRed = (float*)sm2;   // [2][128]
    if ((lane & 3) == 0) {
        #pragma unroll
        for (int i = 0; i < 4; i++) {
            int r = wm * 32 + (i >> 1) * 16 + (i & 1) * 8 + g;
            sRed[wn * 128 + r] = sAcc[i];
        }
    }
    __syncthreads();
    if (tid < 128) atomicAdd(&tOut[P0 + tid], sRed[tid] + sRed[128 + tid]);
}

// ------------------------------------------------------------------
// parallel loss: 40 blocks, double atomics, last-block finalize
#define LOSS_BLOCKS 40
__device__ unsigned int g_lossCnt2;
__global__ void loss_kernel(const float* __restrict__ st_b3, float* __restrict__ out) {
    __shared__ double red[256];
    int t = threadIdx.x;
    float b3 = st_b3[0];
    double s = 0.0;
    for (int i = blockIdx.x * 256 + t; i < NP; i += LOSS_BLOCKS * 256) {
        float tt = g_tT[i] + b3;
        float tp = g_tP[i] + b3;
        s += (double)softplusf(-tt) + (double)softplusf(tp);
    }
    red[t] = s;
    __syncthreads();
    for (int st = 128; st > 0; st >>= 1) { if (t < st) red[t] += red[t + st]; __syncthreads(); }
    if (t == 0) {
        atomicAdd(&g_lossAcc, red[0]);
        __threadfence();
        unsigned int done = atomicAdd(&g_lossCnt2, 1u);
        if (done == LOSS_BLOCKS - 1) {
            g_lossCnt2 = 0u;
            out[LOSS_IDX] = (float)(g_lossAcc / 81920.0);
            out[RATE_IDX] = (float)((double)g_cnt / 16777216.0);
        }
    }
}

// ------------------------------------------------------------------
extern "C" void kernel_launch(void* const* d_in, const int* in_sizes, int n_in,
                              void* d_out, int out_size) {
    const float* feat     = (const float*)d_in[0];
    const float* mlp_w1   = (const float*)d_in[1];
    const float* mlp_w2   = (const float*)d_in[2];
    const float* sp_req_w = (const float*)d_in[3];
    const float* ch_fus_w = (const float*)d_in[4];
    const float* sp_fus_w = (const float*)d_in[5];
    const float* st_w1    = (const float*)d_in[6];
    const float* st_b1    = (const float*)d_in[7];
    const float* st_w2    = (const float*)d_in[8];
    const float* st_b2    = (const float*)d_in[9];
    const float* st_w3    = (const float*)d_in[10];
    const float* st_b3    = (const float*)d_in[11];

    float* out = (float*)d_out;
    float* out_sf = out;
    float* out_sm = out + SM_OFF;

    cudaFuncSetAttribute(gemm1_mma, cudaFuncAttributeMaxDynamicSharedMemorySize, G1_SMEM);
    cudaFuncSetAttribute(gemm2_mma, cudaFuncAttributeMaxDynamicSharedMemorySize, 2 * G2_STAGE);

    prep_kernel<<<(C4 * C4 + 255) / 256, 256>>>(st_w1, st_w2);
    reduce_nc_kernel<<<N_IMG * C_CH, 256>>>(feat);
    reduce_pix_kernel<<<(NP + 255) / 256, 256>>>(feat);
    chcoef_kernel<<<32, 256>>>(mlp_w1, mlp_w2, ch_fus_w);
    spatial_kernel<<<(NP + 255) / 256, 256>>>(sp_req_w);
    spcoef_kernel<<<(4 * HW + 255) / 256, 256>>>(sp_fus_w);
    mask_kernel<<<2048, 256>>>(feat, out_sf, out_sm);

    dim3 g1grid(NP / 128, 2);
    gemm1_mma<<<g1grid, 256, G1_SMEM>>>(st_b1);

    zprep_kernel<<<(HW * (C4 / 8) + 255) / 256, 256>>>();

    dim3 g2grid(NP / 128, 2, 2);
    gemm2_mma<<<g2grid, 256, 2 * G2_STAGE>>>(st_b2, st_w3);

    loss_kernel<<<LOSS_BLOCKS, 256>>>(st_b3, out);
}

// round 16
// speedup vs baseline: 1.0114x; 1.0114x over previous
#include <cuda_runtime.h>
#include <cuda_fp16.h>
#include <cstdint>
#include <math.h>

// ---- problem constants ----
#define N_IMG 5
#define C_CH  256
#define HH    128
#define WWID  128
#define HW    16384
#define NP    81920            // N_IMG * HW
#define C4    1024             // 4*C
#define C2    512              // 2*C
#define THRE  0.01f
#define NCHW_TOT (N_IMG * C_CH * HW)

// output layout: [sparse_feature | loss | rate | sparse_mask]
#define LOSS_IDX 20971520
#define RATE_IDX 20971521
#define SM_OFF   20971522

// gaussian weights
#define G2_C 0.15915494309189535f
#define G2_E 0.09653235263005391f
#define G2_D 0.05855018091964769f
#define G1_C 0.45186276187760605f
#define G1_S 0.27406861906119697f

// ---- device scratch ----
__device__ __align__(16) __half g_Uh[(size_t)NP * C4];   // fp16(U + b1), [p][j]
__device__ __align__(16) __half g_Vh[(size_t)NP * C4];   // fp16(V),      [p][j]
__device__ __align__(16) __half g_ZT[(size_t)NP * C4];   // relu(Uh+Vh)
__device__ __align__(16) __half g_ZP[(size_t)NP * C4];   // relu(Uh_roll+Vh)
__device__ __align__(16) __half g_Fh[(size_t)NCHW_TOT];  // fp16 feat [n][c][p]
__device__ __align__(16) __half g_Sh[(size_t)NCHW_TOT];  // fp16 sparse [n][c][p]
__device__ __align__(16) __half g_W2h[(size_t)C4 * C4];
__device__ __align__(16) __half g_W1h[(size_t)C4 * C2];
__device__ float g_avg[N_IMG * C_CH];
__device__ float g_mx[N_IMG * C_CH];
__device__ float g_chcoef[4 * C_CH];
__device__ float g_cmean[NP];
__device__ float g_cmax[NP];
__device__ float g_spatt[NP];
__device__ float g_act[NP];
__device__ float g_spcoef[4 * HW];
__device__ float g_tT[NP];
__device__ float g_tP[NP];
__device__ unsigned long long g_cnt;
__device__ double g_lossAcc;

__device__ __forceinline__ float sigmoidf(float x) { return 1.f / (1.f + expf(-x)); }
__device__ __forceinline__ float softplusf(float x) { return fmaxf(x, 0.f) + log1pf(expf(-fabsf(x))); }
__device__ __forceinline__ float g2w(int ky, int kx) {
    int d = (ky != 1) + (kx != 1);
    return d == 0 ? G2_C : (d == 1 ? G2_E : G2_D);
}

// ================= mma.sync helpers =================
__device__ __forceinline__ uint32_t smem_u32(const void* p) {
    uint32_t a;
    asm("{ .reg .u64 t; cvta.to.shared.u64 t, %1; cvt.u32.u64 %0, t; }" : "=r"(a) : "l"(p));
    return a;
}
__device__ __forceinline__ void ldsm4(uint32_t& r0, uint32_t& r1, uint32_t& r2, uint32_t& r3, uint32_t a) {
    asm volatile("ldmatrix.sync.aligned.m8n8.x4.shared.b16 {%0,%1,%2,%3}, [%4];"
                 : "=r"(r0), "=r"(r1), "=r"(r2), "=r"(r3) : "r"(a));
}
__device__ __forceinline__ void ldsm4t(uint32_t& r0, uint32_t& r1, uint32_t& r2, uint32_t& r3, uint32_t a) {
    asm volatile("ldmatrix.sync.aligned.m8n8.x4.trans.shared.b16 {%0,%1,%2,%3}, [%4];"
                 : "=r"(r0), "=r"(r1), "=r"(r2), "=r"(r3) : "r"(a));
}
__device__ __forceinline__ void mma_f16(float* c, uint32_t a0, uint32_t a1, uint32_t a2, uint32_t a3,
                                        uint32_t b0, uint32_t b1) {
    asm volatile("mma.sync.aligned.m16n8k16.row.col.f32.f16.f16.f32 "
                 "{%0,%1,%2,%3}, {%4,%5,%6,%7}, {%8,%9}, {%0,%1,%2,%3};"
                 : "+f"(c[0]), "+f"(c[1]), "+f"(c[2]), "+f"(c[3])
                 : "r"(a0), "r"(a1), "r"(a2), "r"(a3), "r"(b0), "r"(b1));
}
__device__ __forceinline__ uint32_t pack2h(float a, float b) {
    __half ha = __float2half_rn(a);
    __half hb = __float2half_rn(b);
    return (uint32_t)__half_as_ushort(ha) | ((uint32_t)__half_as_ushort(hb) << 16);
}
// z = relu(u + v) on packed fp16x2
__device__ __forceinline__ uint32_t hrelu_add2(uint32_t u, uint32_t v) {
    __half2 s = __hadd2(*(__half2*)&u, *(__half2*)&v);
    s = __hmax2(s, __float2half2_rn(0.f));
    return *(uint32_t*)&s;
}

// ------------------------------------------------------------------
// front kernel: prep (zero accums + W1/W2 -> fp16) || reduce_nc || reduce_pix
// all three are independent; merged into one launch so they co-run.
#define PREP_B 4096
#define NC_B   1280
#define PIX_B  320
#define FRONT_B (PREP_B + NC_B + PIX_B)
__global__ void front_kernel(const float* __restrict__ W1, const float* __restrict__ W2,
                             const float* __restrict__ feat) {
    __shared__ float ss[256], sm[256];
    int b = blockIdx.x;
    int t = threadIdx.x;
    if (b < PREP_B) {
        int i = b * 256 + t;
        if (i == 0) { g_cnt = 0ULL; g_lossAcc = 0.0; }
        if (i < NP) { g_tT[i] = 0.f; g_tP[i] = 0.f; }
        if (i < C4 * C4) g_W2h[i] = __float2half_rn(W2[i]);
        if (i < C4 * C2) g_W1h[i] = __float2half_rn(W1[i]);
        return;
    }
    if (b < PREP_B + NC_B) {
        int nc = b - PREP_B;
        const float* base = feat + (size_t)nc * HW;
        float s = 0.f, m = -3.402823466e38f;
        for (int i = t; i < HW; i += 256) { float v = base[i]; s += v; m = fmaxf(m, v); }
        ss[t] = s; sm[t] = m;
        __syncthreads();
        for (int st = 128; st > 0; st >>= 1) {
            if (t < st) { ss[t] += ss[t + st]; sm[t] = fmaxf(sm[t], sm[t + st]); }
            __syncthreads();
        }
        if (t == 0) { g_avg[nc] = ss[0] * (1.f / HW); g_mx[nc] = sm[0]; }
        return;
    }
    {
        int p = (b - PREP_B - NC_B) * 256 + t;
        if (p >= NP) return;
        int n = p >> 14, pix = p & 16383;
        const float* base = feat + (size_t)n * C_CH * HW + pix;
        float s = 0.f, m = -3.402823466e38f;
        #pragma unroll 8
        for (int c = 0; c < C_CH; c++) { float v = base[(size_t)c * HW]; s += v; m = fmaxf(m, v); }
        g_cmean[p] = s * (1.f / C_CH);
        g_cmax[p] = m;
    }
}

// ------------------------------------------------------------------
// ch_coef, parallel: grid = 4 n * 8 c-tiles; hidden layer recomputed per block (tiny)
__global__ void chcoef_kernel(const float* __restrict__ w1, const float* __restrict__ w2,
                              const float* __restrict__ cfw) {
    __shared__ float hsS[N_IMG * 16];
    __shared__ float ego[C_CH];
    __shared__ float att[C_CH];
    __shared__ float tmp[34];
    int t = threadIdx.x;
    int n = blockIdx.x >> 3;          // 0..3
    int cb = blockIdx.x & 7;          // c-tile, 32 c's
    if (t < N_IMG * 16) {
        int nn = t / 16, h = t % 16;
        const float* wr = w1 + h * C_CH;
        const float* av = g_avg + nn * C_CH;
        const float* mv = g_mx + nn * C_CH;
        float sa = 0.f, sm = 0.f;
        for (int c = 0; c < C_CH; c++) { sa += av[c] * wr[c]; sm += mv[c] * wr[c]; }
        hsS[t] = fmaxf(sa, 0.f) + fmaxf(sm, 0.f);
    }
    __syncthreads();
    // ego / att rows (each thread one k)
    {
        float p0 = 0.f, p1 = 0.f;
        const float* w2r = w2 + t * 16;
        #pragma unroll
        for (int h = 0; h < 16; h++) {
            float w = w2r[h];
            p0 += hsS[h] * w;                   // n=0
            p1 += hsS[(n + 1) * 16 + h] * w;    // n+1
        }
        ego[t] = 1.f - sigmoidf(p0);
        att[t] = sigmoidf(p1);
    }
    __syncthreads();
    // 34 halo dots: c = cb*32 - 1 + j, warp per j
    int wid = t >> 5, lane = t & 31;
    for (int j = wid; j < 34; j += 8) {
        int c = cb * 32 - 1 + j;
        if (c < 0 || c > 255) { if (lane == 0) tmp[j] = 0.f; continue; }
        const float* row = cfw + (size_t)c * C2;
        float p = 0.f;
        for (int k = lane; k < C_CH; k += 32)
            p += ego[k] * row[k] + att[k] * row[C_CH + k];
        #pragma unroll
        for (int o = 16; o > 0; o >>= 1) p += __shfl_xor_sync(0xFFFFFFFFu, p, o);
        if (lane == 0) tmp[j] = sigmoidf(p);
    }
    __syncthreads();
    if (t < 32) {
        int c = cb * 32 + t;
        float v = G1_C * tmp[t + 1];
        if (c > 0)   v += G1_S * tmp[t];
        if (c < 255) v += G1_S * tmp[t + 2];
        g_chcoef[n * C_CH + c] = v;
    }
}

__global__ void spatial_kernel(const float* __restrict__ sw) {
    int idx = blockIdx.x * blockDim.x + threadIdx.x;
    if (idx >= NP) return;
    int n = idx >> 14, pix = idx & 16383;
    int h = pix >> 7, w = pix & 127;
    float satt = 0.f, act = 0.f;
    #pragma unroll
    for (int ky = 0; ky < 3; ky++) {
        int hh = h + ky - 1;
        if (hh < 0 || hh >= HH) continue;
        #pragma unroll
        for (int kx = 0; kx < 3; kx++) {
            int ww = w + kx - 1;
            if (ww < 0 || ww >= WWID) continue;
            int q = n * HW + hh * WWID + ww;
            float cm = g_cmean[q], cx = g_cmax[q];
            satt += cm * sw[ky * 3 + kx] + cx * sw[9 + ky * 3 + kx];
            act += g2w(ky, kx) * sigmoidf(cm);
        }
    }
    g_spatt[idx] = sigmoidf(satt);
    g_act[idx] = act;
}

__global__ void spcoef_kernel(const float* __restrict__ spfus) {
    int idx = blockIdx.x * blockDim.x + threadIdx.x;
    if (idx >= 4 * HW) return;
    int m = idx >> 14, pix = idx & 16383;
    int h = pix >> 7, w = pix & 127;
    float wa = spfus[0], wb = spfus[1];
    float acc = 0.f;
    #pragma unroll
    for (int ky = 0; ky < 3; ky++) {
        int hh = h + ky - 1;
        if (hh < 0 || hh >= HH) continue;
        #pragma unroll
        for (int kx = 0; kx < 3; kx++) {
            int ww = w + kx - 1;
            if (ww < 0 || ww >= WWID) continue;
            int q = hh * WWID + ww;
            float pre = wa * (1.f - g_spatt[q]) + wb * g_spatt[(m + 1) * HW + q];
            acc += g2w(ky, kx) * sigmoidf(pre);
        }
    }
    g_spcoef[idx] = acc;
}

// mask + sparse_feature + sparse_mask + fp16 copies of feat & sparse (fused)
__global__ void mask_kernel(const float* __restrict__ feat,
                            float* __restrict__ out_sf, float* __restrict__ out_sm) {
    int t = threadIdx.x;
    unsigned int cnt = 0;
    for (int i2 = blockIdx.x * blockDim.x + t; i2 < NCHW_TOT / 2; i2 += gridDim.x * blockDim.x) {
        int idx = i2 * 2;
        int n = idx / (C_CH * HW);
        float2 f = *(const float2*)(feat + idx);
        float2 sf, sm;
        if (n == 0) { sf = f; sm = make_float2(1.f, 1.f); }
        else {
            int rem = idx - n * C_CH * HW;
            int c = rem >> 14, p = rem & 16383;
            int m = n - 1;
            float cc = g_chcoef[m * C_CH + c];
            float v0 = cc * g_spcoef[m * HW + p] * g_act[n * HW + p];
            float v1 = cc * g_spcoef[m * HW + p + 1] * g_act[n * HW + p + 1];
            bool mk0 = v0 > THRE, mk1 = v1 > THRE;
            sf.x = mk0 ? f.x : 0.f; sm.x = mk0 ? 1.f : 0.f;
            sf.y = mk1 ? f.y : 0.f; sm.y = mk1 ? 1.f : 0.f;
            cnt += (mk0 ? 1u : 0u) + (mk1 ? 1u : 0u);
        }
        *(float2*)(out_sf + idx) = sf;
        *(float2*)(out_sm + idx) = sm;
        *(uint32_t*)&g_Fh[idx] = pack2h(f.x, f.y);
        *(uint32_t*)&g_Sh[idx] = pack2h(sf.x, sf.y);
    }
    __shared__ unsigned int sc[256];
    sc[t] = cnt;
    __syncthreads();
    for (int s = 128; s > 0; s >>= 1) { if (t < s) sc[t] += sc[t + s]; __syncthreads(); }
    if (t == 0) atomicAdd(&g_cnt, (unsigned long long)sc[0]);
}

// ------------------------------------------------------------------
// z = relu(Uh[roll]+Vh) for both rolls; each thread owns one (pix,k8) column
// across all 5 images so Uh/Vh are read exactly once.
__global__ void zprep_kernel() {
    int i = blockIdx.x * blockDim.x + threadIdx.x;   // 0 .. 16384*128-1
    if (i >= HW * (C4 / 8)) return;
    int pix = i >> 7;
    int k = (i & 127) * 8;
    uint4 u[N_IMG], v[N_IMG];
    #pragma unroll
    for (int n = 0; n < N_IMG; n++) {
        size_t e = ((((size_t)n << 14) | pix) << 10) | k;
        u[n] = *(const uint4*)(g_Uh + e);
        v[n] = *(const uint4*)(g_Vh + e);
    }
    #pragma unroll
    for (int n = 0; n < N_IMG; n++) {
        int nr = (n + 1 == N_IMG) ? 0 : n + 1;
        size_t e = ((((size_t)n << 14) | pix) << 10) | k;
        uint4 zt, zp;
        zt.x = hrelu_add2(u[n].x, v[n].x);  zp.x = hrelu_add2(u[nr].x, v[n].x);
        zt.y = hrelu_add2(u[n].y, v[n].y);  zp.y = hrelu_add2(u[nr].y, v[n].y);
        zt.z = hrelu_add2(u[n].z, v[n].z);  zp.z = hrelu_add2(u[nr].z, v[n].z);
        zt.w = hrelu_add2(u[n].w, v[n].w);  zp.w = hrelu_add2(u[nr].w, v[n].w);
        *(uint4*)(g_ZT + e) = zt;
        *(uint4*)(g_ZP + e) = zp;
    }
}

// ==================================================================
// GEMM1 (mma.sync fp16, A-resident, jt-split for tail smoothing):
// Uh[p][j] = fp16(sum_c A*W1a + b1), Vh = fp16(sum_c A*W1b)
// Block per (P0, which, jt-half); A tile [k=256][m=128] resident in smem;
// jt loop (4 tiles) streams W1 (double-buffered [n=128][k=32] rows 80B).
#define G1_A_OF 0
#define G1_W_OF 69632
#define G1_W_STAGE 10240
#define G1_SMEM (69632 + 2 * 10240)
__global__ __launch_bounds__(256, 2) void gemm1_mma(const float* __restrict__ b1) {
    extern __shared__ __align__(16) char sm1[];
    const int tid = threadIdx.x;
    const int wid = tid >> 5, lane = tid & 31;
    const int wm = wid & 3, wn = wid >> 2;
    const int g = lane >> 2, t2 = (lane & 3) * 2;
    const size_t P0 = (size_t)blockIdx.x * 128;
    const int which = blockIdx.y;              // 0: U from feat, 1: V from sparse
    const int jh = blockIdx.z;                 // jt half: [jh*4, jh*4+4)
    const int n = (int)(P0 >> 14), pl = (int)(P0 & 16383);
    const __half* Ah = (which ? g_Sh : g_Fh) + (size_t)n * C_CH * HW + pl;
    __half* Out = which ? g_Vh : g_Uh;
    const uint32_t sb = smem_u32(sm1);

    // load full A tile resident: 256 k-rows x 128 m, 272B rows
    #pragma unroll
    for (int i = 0; i < 16; i++) {
        int s = tid + 256 * i;
        int r = s >> 4, q = s & 15;
        uint4 v = *(const uint4*)(Ah + (size_t)r * HW + q * 8);
        *(uint4*)(sm1 + G1_A_OF + r * 272 + q * 16) = v;
    }

    for (int jt = jh * 4; jt < jh * 4 + 4; jt++) {
        const __half* Bh = g_W1h + (size_t)jt * 128 * C2 + (which ? 256 : 0);
        float acc[2][8][4];
        #pragma unroll
        for (int a = 0; a < 2; a++)
            #pragma unroll
            for (int b = 0; b < 8; b++)
                #pragma unroll
                for (int c = 0; c < 4; c++) acc[a][b][c] = 0.f;

        uint4 pw[2];
        // W stage 0
        #pragma unroll
        for (int i = 0; i < 2; i++) {
            int s = tid + 256 * i;
            int o = s >> 2, qq = s & 3;
            pw[i] = *(const uint4*)(Bh + (size_t)o * C2 + qq * 8);
        }
        #pragma unroll
        for (int i = 0; i < 2; i++) {
            int s = tid + 256 * i;
            int o = s >> 2, qq = s & 3;
            *(uint4*)(sm1 + G1_W_OF + o * 80 + qq * 16) = pw[i];
        }
        __syncthreads();   // A + W stage resident; also guards W buf reuse across jt

        for (int kc = 0; kc < 8; kc++) {
            if (kc + 1 < 8) {
                int k0 = (kc + 1) * 32;
                #pragma unroll
                for (int i = 0; i < 2; i++) {
                    int s = tid + 256 * i;
                    int o = s >> 2, qq = s & 3;
                    pw[i] = *(const uint4*)(Bh + (size_t)o * C2 + k0 + qq * 8);
                }
            }
            const uint32_t wbase = sb + G1_W_OF + (kc & 1) * G1_W_STAGE;
            #pragma unroll
            for (int ks = 0; ks < 2; ks++) {
                uint32_t bh[8][2];
                #pragma unroll
                for (int np = 0; np < 4; np++) {
                    int row = wn * 64 + np * 16 + (lane & 7) + ((lane >> 4) & 1) * 8;
                    uint32_t col = ks * 32 + ((lane >> 3) & 1) * 16;
                    uint32_t a = wbase + row * 80 + col;
                    ldsm4(bh[2 * np][0], bh[2 * np][1], bh[2 * np + 1][0], bh[2 * np + 1][1], a);
                }
                #pragma unroll
                for (int mf = 0; mf < 2; mf++) {
                    int rowk = kc * 32 + ks * 16 + ((lane >> 4) & 1) * 8 + (lane & 7);
                    uint32_t col = (wm * 32 + mf * 16 + ((lane >> 3) & 1) * 8) * 2;
                    uint32_t a = sb + G1_A_OF + rowk * 272 + col;
                    uint32_t a0, a1, a2, a3;
                    ldsm4t(a0, a1, a2, a3, a);
                    #pragma unroll
                    for (int nf = 0; nf < 8; nf++)
                        mma_f16(acc[mf][nf], a0, a1, a2, a3, bh[nf][0], bh[nf][1]);
                }
            }
            if (kc + 1 < 8) {
                char* buf = sm1 + G1_W_OF + ((kc + 1) & 1) * G1_W_STAGE;
                #pragma unroll
                for (int i = 0; i < 2; i++) {
                    int s = tid + 256 * i;
                    int o = s >> 2, qq = s & 3;
                    *(uint4*)(buf + o * 80 + qq * 16) = pw[i];
                }
            }
            __syncthreads();
        }

        // write Out fp16 [p][j]; fold b1 into the U branch
        #pragma unroll
        for (int mf = 0; mf < 2; mf++) {
            #pragma unroll
            for (int nf = 0; nf < 8; nf++) {
                size_t r0 = P0 + wm * 32 + mf * 16 + g;
                int col = jt * 128 + wn * 64 + nf * 8 + t2;
                float ba = 0.f, bb = 0.f;
                if (which == 0) { ba = __ldg(b1 + col); bb = __ldg(b1 + col + 1); }
                *(uint32_t*)&Out[r0 * C4 + col] = pack2h(acc[mf][nf][0] + ba, acc[mf][nf][1] + bb);
                *(uint32_t*)&Out[(r0 + 8) * C4 + col] = pack2h(acc[mf][nf][2] + ba, acc[mf][nf][3] + bb);
            }
        }
    }
}

// ==================================================================
// GEMM2 (mma.sync fp16, o-split for tail smoothing):
// grid (NP/128, 2 rolls, 2 o-halves); each block does 4 o-tiles and
// atomicAdds its partial T into g_tT/g_tP (exactly 2 contributors/pixel -> deterministic).
#define G2_A_OF 0
#define G2_B_OF 10240
#define G2_STAGE 20480
__global__ __launch_bounds__(256, 2) void gemm2_mma(const float* __restrict__ b2,
                                                    const float* __restrict__ w3) {
    extern __shared__ __align__(16) char sm2[];
    const int tid = threadIdx.x;
    const int wid = tid >> 5, lane = tid & 31;
    const int wm = wid & 3, wn = wid >> 2;
    const int g = lane >> 2, t2 = (lane & 3) * 2;
    const size_t P0 = (size_t)blockIdx.x * 128;
    const int roll = blockIdx.y;
    const int oh = blockIdx.z;                 // o-half: nt in [oh*4, oh*4+4)
    const __half* Z = (roll ? g_ZP : g_ZT) + P0 * C4;
    float* tOut = roll ? g_tP : g_tT;
    const uint32_t sb = smem_u32(sm2);

    float sAcc[4] = {0.f, 0.f, 0.f, 0.f};

    for (int nt = oh * 4; nt < oh * 4 + 4; nt++) {
        const int o0 = nt * 128;
        const __half* Wh = g_W2h + (size_t)o0 * C4;
        float acc[2][8][4];
        #pragma unroll
        for (int a = 0; a < 2; a++)
            #pragma unroll
            for (int b = 0; b < 8; b++)
                #pragma unroll
                for (int c = 0; c < 4; c++) acc[a][b][c] = 0.f;

        uint4 pa[2], pw[2];
        {
            #pragma unroll
            for (int i = 0; i < 2; i++) {
                int s = tid + 256 * i;
                int p = s >> 2, q = s & 3;
                pa[i] = *(const uint4*)(Z + (size_t)p * C4 + q * 8);
                pw[i] = *(const uint4*)(Wh + (size_t)p * C4 + q * 8);
            }
            char* buf = sm2;
            #pragma unroll
            for (int i = 0; i < 2; i++) {
                int s = tid + 256 * i;
                int p = s >> 2, q = s & 3;
                *(uint4*)(buf + G2_A_OF + p * 80 + q * 16) = pa[i];
                *(uint4*)(buf + G2_B_OF + p * 80 + q * 16) = pw[i];
            }
        }
        __syncthreads();

        for (int kc = 0; kc < 32; kc++) {
            if (kc + 1 < 32) {
                int k0 = (kc + 1) * 32;
                #pragma unroll
                for (int i = 0; i < 2; i++) {
                    int s = tid + 256 * i;
                    int p = s >> 2, q = s & 3;
                    pa[i] = *(const uint4*)(Z + (size_t)p * C4 + k0 + q * 8);
                    pw[i] = *(const uint4*)(Wh + (size_t)p * C4 + k0 + q * 8);
                }
            }
            const uint32_t base = sb + (kc & 1) * G2_STAGE;
            #pragma unroll
            for (int ks = 0; ks < 2; ks++) {
                uint32_t bh[8][2];
                #pragma unroll
                for (int np = 0; np < 4; np++) {
                    int row = wn * 64 + np * 16 + (lane & 7) + ((lane >> 4) & 1) * 8;
                    uint32_t col = ks * 32 + ((lane >> 3) & 1) * 16;
                    uint32_t a = base + G2_B_OF + row * 80 + col;
                    ldsm4(bh[2 * np][0], bh[2 * np][1], bh[2 * np + 1][0], bh[2 * np + 1][1], a);
                }
                #pragma unroll
                for (int mf = 0; mf < 2; mf++) {
                    int row = wm * 32 + mf * 16 + (lane & 7) + ((lane >> 3) & 1) * 8;
                    uint32_t col = ks * 32 + ((lane >> 4) & 1) * 16;
                    uint32_t a = base + G2_A_OF + row * 80 + col;
                    uint32_t a0, a1, a2, a3;
                    ldsm4(a0, a1, a2, a3, a);
                    #pragma unroll
                    for (int nf = 0; nf < 8; nf++)
                        mma_f16(acc[mf][nf], a0, a1, a2, a3, bh[nf][0], bh[nf][1]);
                }
            }
            if (kc + 1 < 32) {
                char* buf = sm2 + ((kc + 1) & 1) * G2_STAGE;
                #pragma unroll
                for (int i = 0; i < 2; i++) {
                    int s = tid + 256 * i;
                    int p = s >> 2, q = s & 3;
                    *(uint4*)(buf + G2_A_OF + p * 80 + q * 16) = pa[i];
                    *(uint4*)(buf + G2_B_OF + p * 80 + q * 16) = pw[i];
                }
            }
            __syncthreads();
        }

        // fold this o-tile into per-pixel scalars
        #pragma unroll
        for (int mf = 0; mf < 2; mf++) {
            #pragma unroll
            for (int nf = 0; nf < 8; nf++) {
                int c0 = o0 + wn * 64 + nf * 8 + t2;
                float b2a = __ldg(b2 + c0), b2b = __ldg(b2 + c0 + 1);
                float w3a = __ldg(w3 + c0), w3b = __ldg(w3 + c0 + 1);
                sAcc[mf * 2 + 0] += fmaxf(acc[mf][nf][0] + b2a, 0.f) * w3a
                                  + fmaxf(acc[mf][nf][1] + b2b, 0.f) * w3b;
                sAcc[mf * 2 + 1] += fmaxf(acc[mf][nf][2] + b2a, 0.f) * w3a
                                  + fmaxf(acc[mf][nf][3] + b2b, 0.f) * w3b;
            }
        }
    }

    // reduce across the 4-lane groups (same rows, different cols)
    #pragma unroll
    for (int i = 0; i < 4; i++) {
        sAcc[i] += __shfl_xor_sync(0xFFFFFFFFu, sAcc[i], 1);
        sAcc[i] += __shfl_xor_sync(0xFFFFFFFFu, sAcc[i], 2);
    }
    __syncthreads();
    float* sRed = (float*)sm2;   // [2][128]
    if ((lane & 3) == 0) {
        #pragma unroll
        for (int i = 0; i < 4; i++) {
            int r = wm * 32 + (i >> 1) * 16 + (i & 1) * 8 + g;
            sRed[wn * 128 + r] = sAcc[i];
        }
    }
    __syncthreads();
    if (tid < 128) atomicAdd(&tOut[P0 + tid], sRed[tid] + sRed[128 + tid]);
}

// ------------------------------------------------------------------
// parallel loss: 40 blocks, double atomics, last-block finalize
#define LOSS_BLOCKS 40
__device__ unsigned int g_lossCnt2;
__global__ void loss_kernel(const float* __restrict__ st_b3, float* __restrict__ out) {
    __shared__ double red[256];
    int t = threadIdx.x;
    float b3 = st_b3[0];
    double s = 0.0;
    for (int i = blockIdx.x * 256 + t; i < NP; i += LOSS_BLOCKS * 256) {
        float tt = g_tT[i] + b3;
        float tp = g_tP[i] + b3;
        s += (double)softplusf(-tt) + (double)softplusf(tp);
    }
    red[t] = s;
    __syncthreads();
    for (int st = 128; st > 0; st >>= 1) { if (t < st) red[t] += red[t + st]; __syncthreads(); }
    if (t == 0) {
        atomicAdd(&g_lossAcc, red[0]);
        __threadfence();
        unsigned int done = atomicAdd(&g_lossCnt2, 1u);
        if (done == LOSS_BLOCKS - 1) {
            g_lossCnt2 = 0u;
            out[LOSS_IDX] = (float)(g_lossAcc / 81920.0);
            out[RATE_IDX] = (float)((double)g_cnt / 16777216.0);
        }
    }
}

// ------------------------------------------------------------------
extern "C" void kernel_launch(void* const* d_in, const int* in_sizes, int n_in,
                              void* d_out, int out_size) {
    const float* feat     = (const float*)d_in[0];
    const float* mlp_w1   = (const float*)d_in[1];
    const float* mlp_w2   = (const float*)d_in[2];
    const float* sp_req_w = (const float*)d_in[3];
    const float* ch_fus_w = (const float*)d_in[4];
    const float* sp_fus_w = (const float*)d_in[5];
    const float* st_w1    = (const float*)d_in[6];
    const float* st_b1    = (const float*)d_in[7];
    const float* st_w2    = (const float*)d_in[8];
    const float* st_b2    = (const float*)d_in[9];
    const float* st_w3    = (const float*)d_in[10];
    const float* st_b3    = (const float*)d_in[11];

    float* out = (float*)d_out;
    float* out_sf = out;
    float* out_sm = out + SM_OFF;

    cudaFuncSetAttribute(gemm1_mma, cudaFuncAttributeMaxDynamicSharedMemorySize, G1_SMEM);
    cudaFuncSetAttribute(gemm2_mma, cudaFuncAttributeMaxDynamicSharedMemorySize, 2 * G2_STAGE);

    front_kernel<<<FRONT_B, 256>>>(st_w1, st_w2, feat);
    chcoef_kernel<<<32, 256>>>(mlp_w1, mlp_w2, ch_fus_w);
    spatial_kernel<<<(NP + 255) / 256, 256>>>(sp_req_w);
    spcoef_kernel<<<(4 * HW + 255) / 256, 256>>>(sp_fus_w);
    mask_kernel<<<2048, 256>>>(feat, out_sf, out_sm);

    dim3 g1grid(NP / 128, 2, 2);
    gemm1_mma<<<g1grid, 256, G1_SMEM>>>(st_b1);

    zprep_kernel<<<(HW * (C4 / 8) + 255) / 256, 256>>>();

    dim3 g2grid(NP / 128, 2, 2);
    gemm2_mma<<<g2grid, 256, 2 * G2_STAGE>>>(st_b2, st_w3);

    loss_kernel<<<LOSS_BLOCKS, 256>>>(st_b3, out);
}

// round 17
// speedup vs baseline: 1.0150x; 1.0035x over previous
#include <cuda_runtime.h>
#include <cuda_fp16.h>
#include <cstdint>
#include <math.h>

// ---- problem constants ----
#define N_IMG 5
#define C_CH  256
#define HH    128
#define WWID  128
#define HW    16384
#define NP    81920            // N_IMG * HW
#define C4    1024             // 4*C
#define C2    512              // 2*C
#define THRE  0.01f
#define NCHW_TOT (N_IMG * C_CH * HW)

// output layout: [sparse_feature | loss | rate | sparse_mask]
#define LOSS_IDX 20971520
#define RATE_IDX 20971521
#define SM_OFF   20971522

// gaussian weights
#define G2_C 0.15915494309189535f
#define G2_E 0.09653235263005391f
#define G2_D 0.05855018091964769f
#define G1_C 0.45186276187760605f
#define G1_S 0.27406861906119697f

// ---- device scratch ----
__device__ __align__(16) __half g_Uh[(size_t)NP * C4];   // fp16(U + b1), [p][j]
__device__ __align__(16) __half g_Vh[(size_t)NP * C4];   // fp16(V),      [p][j]
__device__ __align__(16) __half g_ZT[(size_t)NP * C4];   // relu(Uh+Vh)
__device__ __align__(16) __half g_ZP[(size_t)NP * C4];   // relu(Uh_roll+Vh)
__device__ __align__(16) __half g_Fh[(size_t)NCHW_TOT];  // fp16 feat [n][c][p]
__device__ __align__(16) __half g_Sh[(size_t)NCHW_TOT];  // fp16 sparse [n][c][p]
__device__ __align__(16) __half g_W2h[(size_t)C4 * C4];
__device__ __align__(16) __half g_W1h[(size_t)C4 * C2];
__device__ float g_avg[N_IMG * C_CH];
__device__ float g_mx[N_IMG * C_CH];
__device__ float g_chcoef[4 * C_CH];
__device__ float g_cmean[NP];
__device__ float g_cmax[NP];
__device__ float g_spatt[NP];
__device__ float g_act[NP];
__device__ float g_spcoef[4 * HW];
__device__ float g_tT[NP];
__device__ float g_tP[NP];
__device__ unsigned long long g_cnt;
__device__ double g_lossAcc;

__device__ __forceinline__ float sigmoidf(float x) { return 1.f / (1.f + expf(-x)); }
__device__ __forceinline__ float softplusf(float x) { return fmaxf(x, 0.f) + log1pf(expf(-fabsf(x))); }
__device__ __forceinline__ float g2w(int ky, int kx) {
    int d = (ky != 1) + (kx != 1);
    return d == 0 ? G2_C : (d == 1 ? G2_E : G2_D);
}

// ================= mma.sync helpers =================
__device__ __forceinline__ uint32_t smem_u32(const void* p) {
    uint32_t a;
    asm("{ .reg .u64 t; cvta.to.shared.u64 t, %1; cvt.u32.u64 %0, t; }" : "=r"(a) : "l"(p));
    return a;
}
__device__ __forceinline__ void ldsm4(uint32_t& r0, uint32_t& r1, uint32_t& r2, uint32_t& r3, uint32_t a) {
    asm volatile("ldmatrix.sync.aligned.m8n8.x4.shared.b16 {%0,%1,%2,%3}, [%4];"
                 : "=r"(r0), "=r"(r1), "=r"(r2), "=r"(r3) : "r"(a));
}
__device__ __forceinline__ void ldsm4t(uint32_t& r0, uint32_t& r1, uint32_t& r2, uint32_t& r3, uint32_t a) {
    asm volatile("ldmatrix.sync.aligned.m8n8.x4.trans.shared.b16 {%0,%1,%2,%3}, [%4];"
                 : "=r"(r0), "=r"(r1), "=r"(r2), "=r"(r3) : "r"(a));
}
__device__ __forceinline__ void mma_f16(float* c, uint32_t a0, uint32_t a1, uint32_t a2, uint32_t a3,
                                        uint32_t b0, uint32_t b1) {
    asm volatile("mma.sync.aligned.m16n8k16.row.col.f32.f16.f16.f32 "
                 "{%0,%1,%2,%3}, {%4,%5,%6,%7}, {%8,%9}, {%0,%1,%2,%3};"
                 : "+f"(c[0]), "+f"(c[1]), "+f"(c[2]), "+f"(c[3])
                 : "r"(a0), "r"(a1), "r"(a2), "r"(a3), "r"(b0), "r"(b1));
}
__device__ __forceinline__ uint32_t pack2h(float a, float b) {
    __half ha = __float2half_rn(a);
    __half hb = __float2half_rn(b);
    return (uint32_t)__half_as_ushort(ha) | ((uint32_t)__half_as_ushort(hb) << 16);
}
// z = relu(u + v) on packed fp16x2
__device__ __forceinline__ uint32_t hrelu_add2(uint32_t u, uint32_t v) {
    __half2 s = __hadd2(*(__half2*)&u, *(__half2*)&v);
    s = __hmax2(s, __float2half2_rn(0.f));
    return *(uint32_t*)&s;
}

// ------------------------------------------------------------------
// front kernel: prep (zero accums + W1/W2 -> fp16) || reduce_nc || reduce_pix
#define PREP_B 4096
#define NC_B   1280
#define PIX_B  320
#define FRONT_B (PREP_B + NC_B + PIX_B)
__global__ void front_kernel(const float* __restrict__ W1, const float* __restrict__ W2,
                             const float* __restrict__ feat) {
    __shared__ float ss[256], sm[256];
    int b = blockIdx.x;
    int t = threadIdx.x;
    if (b < PREP_B) {
        int i = b * 256 + t;
        if (i == 0) { g_cnt = 0ULL; g_lossAcc = 0.0; }
        if (i < NP) { g_tT[i] = 0.f; g_tP[i] = 0.f; }
        if (i < C4 * C4) g_W2h[i] = __float2half_rn(W2[i]);
        if (i < C4 * C2) g_W1h[i] = __float2half_rn(W1[i]);
        return;
    }
    if (b < PREP_B + NC_B) {
        int nc = b - PREP_B;
        const float* base = feat + (size_t)nc * HW;
        float s = 0.f, m = -3.402823466e38f;
        for (int i = t; i < HW; i += 256) { float v = base[i]; s += v; m = fmaxf(m, v); }
        ss[t] = s; sm[t] = m;
        __syncthreads();
        for (int st = 128; st > 0; st >>= 1) {
            if (t < st) { ss[t] += ss[t + st]; sm[t] = fmaxf(sm[t], sm[t + st]); }
            __syncthreads();
        }
        if (t == 0) { g_avg[nc] = ss[0] * (1.f / HW); g_mx[nc] = sm[0]; }
        return;
    }
    {
        int p = (b - PREP_B - NC_B) * 256 + t;
        if (p >= NP) return;
        int n = p >> 14, pix = p & 16383;
        const float* base = feat + (size_t)n * C_CH * HW + pix;
        float s = 0.f, m = -3.402823466e38f;
        #pragma unroll 8
        for (int c = 0; c < C_CH; c++) { float v = base[(size_t)c * HW]; s += v; m = fmaxf(m, v); }
        g_cmean[p] = s * (1.f / C_CH);
        g_cmax[p] = m;
    }
}

// ------------------------------------------------------------------
// merged: chcoef (blocks 0..31, independent) || spatial (blocks 32..351)
// both depend only on front_kernel outputs.
#define CH_B 32
#define SPA_B 320
__global__ void chcoef_spatial_kernel(const float* __restrict__ w1, const float* __restrict__ w2,
                                      const float* __restrict__ cfw, const float* __restrict__ sw) {
    int b = blockIdx.x;
    int t = threadIdx.x;
    if (b < CH_B) {
        // ---- chcoef ----
        __shared__ float hsS[N_IMG * 16];
        __shared__ float ego[C_CH];
        __shared__ float att[C_CH];
        __shared__ float tmp[34];
        int n = b >> 3;          // 0..3
        int cb = b & 7;          // c-tile, 32 c's
        if (t < N_IMG * 16) {
            int nn = t / 16, h = t % 16;
            const float* wr = w1 + h * C_CH;
            const float* av = g_avg + nn * C_CH;
            const float* mv = g_mx + nn * C_CH;
            float sa = 0.f, sm = 0.f;
            for (int c = 0; c < C_CH; c++) { sa += av[c] * wr[c]; sm += mv[c] * wr[c]; }
            hsS[t] = fmaxf(sa, 0.f) + fmaxf(sm, 0.f);
        }
        __syncthreads();
        {
            float p0 = 0.f, p1 = 0.f;
            const float* w2r = w2 + t * 16;
            #pragma unroll
            for (int h = 0; h < 16; h++) {
                float w = w2r[h];
                p0 += hsS[h] * w;                   // n=0
                p1 += hsS[(n + 1) * 16 + h] * w;    // n+1
            }
            ego[t] = 1.f - sigmoidf(p0);
            att[t] = sigmoidf(p1);
        }
        __syncthreads();
        int wid = t >> 5, lane = t & 31;
        for (int j = wid; j < 34; j += 8) {
            int c = cb * 32 - 1 + j;
            if (c < 0 || c > 255) { if (lane == 0) tmp[j] = 0.f; continue; }
            const float* row = cfw + (size_t)c * C2;
            float p = 0.f;
            for (int k = lane; k < C_CH; k += 32)
                p += ego[k] * row[k] + att[k] * row[C_CH + k];
            #pragma unroll
            for (int o = 16; o > 0; o >>= 1) p += __shfl_xor_sync(0xFFFFFFFFu, p, o);
            if (lane == 0) tmp[j] = sigmoidf(p);
        }
        __syncthreads();
        if (t < 32) {
            int c = cb * 32 + t;
            float v = G1_C * tmp[t + 1];
            if (c > 0)   v += G1_S * tmp[t];
            if (c < 255) v += G1_S * tmp[t + 2];
            g_chcoef[n * C_CH + c] = v;
        }
        return;
    }
    // ---- spatial ----
    int idx = (b - CH_B) * 256 + t;
    if (idx >= NP) return;
    int n = idx >> 14, pix = idx & 16383;
    int h = pix >> 7, w = pix & 127;
    float satt = 0.f, act = 0.f;
    #pragma unroll
    for (int ky = 0; ky < 3; ky++) {
        int hh = h + ky - 1;
        if (hh < 0 || hh >= HH) continue;
        #pragma unroll
        for (int kx = 0; kx < 3; kx++) {
            int ww = w + kx - 1;
            if (ww < 0 || ww >= WWID) continue;
            int q = n * HW + hh * WWID + ww;
            float cm = g_cmean[q], cx = g_cmax[q];
            satt += cm * sw[ky * 3 + kx] + cx * sw[9 + ky * 3 + kx];
            act += g2w(ky, kx) * sigmoidf(cm);
        }
    }
    g_spatt[idx] = sigmoidf(satt);
    g_act[idx] = act;
}

__global__ void spcoef_kernel(const float* __restrict__ spfus) {
    int idx = blockIdx.x * blockDim.x + threadIdx.x;
    if (idx >= 4 * HW) return;
    int m = idx >> 14, pix = idx & 16383;
    int h = pix >> 7, w = pix & 127;
    float wa = spfus[0], wb = spfus[1];
    float acc = 0.f;
    #pragma unroll
    for (int ky = 0; ky < 3; ky++) {
        int hh = h + ky - 1;
        if (hh < 0 || hh >= HH) continue;
        #pragma unroll
        for (int kx = 0; kx < 3; kx++) {
            int ww = w + kx - 1;
            if (ww < 0 || ww >= WWID) continue;
            int q = hh * WWID + ww;
            float pre = wa * (1.f - g_spatt[q]) + wb * g_spatt[(m + 1) * HW + q];
            acc += g2w(ky, kx) * sigmoidf(pre);
        }
    }
    g_spcoef[idx] = acc;
}

// mask + sparse_feature + sparse_mask + fp16 copies of feat & sparse (fused)
__global__ void mask_kernel(const float* __restrict__ feat,
                            float* __restrict__ out_sf, float* __restrict__ out_sm) {
    int t = threadIdx.x;
    unsigned int cnt = 0;
    for (int i2 = blockIdx.x * blockDim.x + t; i2 < NCHW_TOT / 2; i2 += gridDim.x * blockDim.x) {
        int idx = i2 * 2;
        int n = idx / (C_CH * HW);
        float2 f = *(const float2*)(feat + idx);
        float2 sf, sm;
        if (n == 0) { sf = f; sm = make_float2(1.f, 1.f); }
        else {
            int rem = idx - n * C_CH * HW;
            int c = rem >> 14, p = rem & 16383;
            int m = n - 1;
            float cc = g_chcoef[m * C_CH + c];
            float v0 = cc * g_spcoef[m * HW + p] * g_act[n * HW + p];
            float v1 = cc * g_spcoef[m * HW + p + 1] * g_act[n * HW + p + 1];
            bool mk0 = v0 > THRE, mk1 = v1 > THRE;
            sf.x = mk0 ? f.x : 0.f; sm.x = mk0 ? 1.f : 0.f;
            sf.y = mk1 ? f.y : 0.f; sm.y = mk1 ? 1.f : 0.f;
            cnt += (mk0 ? 1u : 0u) + (mk1 ? 1u : 0u);
        }
        *(float2*)(out_sf + idx) = sf;
        *(float2*)(out_sm + idx) = sm;
        *(uint32_t*)&g_Fh[idx] = pack2h(f.x, f.y);
        *(uint32_t*)&g_Sh[idx] = pack2h(sf.x, sf.y);
    }
    __shared__ unsigned int sc[256];
    sc[t] = cnt;
    __syncthreads();
    for (int s = 128; s > 0; s >>= 1) { if (t < s) sc[t] += sc[t + s]; __syncthreads(); }
    if (t == 0) atomicAdd(&g_cnt, (unsigned long long)sc[0]);
}

// ------------------------------------------------------------------
// z = relu(Uh[roll]+Vh) for both rolls; each thread owns one (pix,k8) column
// across all 5 images so Uh/Vh are read exactly once.
__global__ void zprep_kernel() {
    int i = blockIdx.x * blockDim.x + threadIdx.x;   // 0 .. 16384*128-1
    if (i >= HW * (C4 / 8)) return;
    int pix = i >> 7;
    int k = (i & 127) * 8;
    uint4 u[N_IMG], v[N_IMG];
    #pragma unroll
    for (int n = 0; n < N_IMG; n++) {
        size_t e = ((((size_t)n << 14) | pix) << 10) | k;
        u[n] = *(const uint4*)(g_Uh + e);
        v[n] = *(const uint4*)(g_Vh + e);
    }
    #pragma unroll
    for (int n = 0; n < N_IMG; n++) {
        int nr = (n + 1 == N_IMG) ? 0 : n + 1;
        size_t e = ((((size_t)n << 14) | pix) << 10) | k;
        uint4 zt, zp;
        zt.x = hrelu_add2(u[n].x, v[n].x);  zp.x = hrelu_add2(u[nr].x, v[n].x);
        zt.y = hrelu_add2(u[n].y, v[n].y);  zp.y = hrelu_add2(u[nr].y, v[n].y);
        zt.z = hrelu_add2(u[n].z, v[n].z);  zp.z = hrelu_add2(u[nr].z, v[n].z);
        zt.w = hrelu_add2(u[n].w, v[n].w);  zp.w = hrelu_add2(u[nr].w, v[n].w);
        *(uint4*)(g_ZT + e) = zt;
        *(uint4*)(g_ZP + e) = zp;
    }
}

// ==================================================================
// GEMM1 (mma.sync fp16, A-resident, jt-split for tail smoothing):
// Uh[p][j] = fp16(sum_c A*W1a + b1), Vh = fp16(sum_c A*W1b)
// Block per (P0, which, jt-half); A tile [k=256][m=128] resident in smem;
// jt loop (4 tiles) streams W1 (double-buffered [n=128][k=32] rows 80B).
#define G1_A_OF 0
#define G1_W_OF 69632
#define G1_W_STAGE 10240
#define G1_SMEM (69632 + 2 * 10240)
__global__ __launch_bounds__(256, 2) void gemm1_mma(const float* __restrict__ b1) {
    extern __shared__ __align__(16) char sm1[];
    const int tid = threadIdx.x;
    const int wid = tid >> 5, lane = tid & 31;
    const int wm = wid & 3, wn = wid >> 2;
    const int g = lane >> 2, t2 = (lane & 3) * 2;
    const size_t P0 = (size_t)blockIdx.x * 128;
    const int which = blockIdx.y;              // 0: U from feat, 1: V from sparse
    const int jh = blockIdx.z;                 // jt half: [jh*4, jh*4+4)
    const int n = (int)(P0 >> 14), pl = (int)(P0 & 16383);
    const __half* Ah = (which ? g_Sh : g_Fh) + (size_t)n * C_CH * HW + pl;
    __half* Out = which ? g_Vh : g_Uh;
    const uint32_t sb = smem_u32(sm1);

    // load full A tile resident: 256 k-rows x 128 m, 272B rows
    #pragma unroll
    for (int i = 0; i < 16; i++) {
        int s = tid + 256 * i;
        int r = s >> 4, q = s & 15;
        uint4 v = *(const uint4*)(Ah + (size_t)r * HW + q * 8);
        *(uint4*)(sm1 + G1_A_OF + r * 272 + q * 16) = v;
    }

    for (int jt = jh * 4; jt < jh * 4 + 4; jt++) {
        const __half* Bh = g_W1h + (size_t)jt * 128 * C2 + (which ? 256 : 0);
        float acc[2][8][4];
        #pragma unroll
        for (int a = 0; a < 2; a++)
            #pragma unroll
            for (int b = 0; b < 8; b++)
                #pragma unroll
                for (int c = 0; c < 4; c++) acc[a][b][c] = 0.f;

        uint4 pw[2];
        // W stage 0
        #pragma unroll
        for (int i = 0; i < 2; i++) {
            int s = tid + 256 * i;
            int o = s >> 2, qq = s & 3;
            pw[i] = *(const uint4*)(Bh + (size_t)o * C2 + qq * 8);
        }
        #pragma unroll
        for (int i = 0; i < 2; i++) {
            int s = tid + 256 * i;
            int o = s >> 2, qq = s & 3;
            *(uint4*)(sm1 + G1_W_OF + o * 80 + qq * 16) = pw[i];
        }
        __syncthreads();   // A + W stage resident; also guards W buf reuse across jt

        for (int kc = 0; kc < 8; kc++) {
            if (kc + 1 < 8) {
                int k0 = (kc + 1) * 32;
                #pragma unroll
                for (int i = 0; i < 2; i++) {
                    int s = tid + 256 * i;
                    int o = s >> 2, qq = s & 3;
                    pw[i] = *(const uint4*)(Bh + (size_t)o * C2 + k0 + qq * 8);
                }
            }
            const uint32_t wbase = sb + G1_W_OF + (kc & 1) * G1_W_STAGE;
            #pragma unroll
            for (int ks = 0; ks < 2; ks++) {
                uint32_t bh[8][2];
                #pragma unroll
                for (int np = 0; np < 4; np++) {
                    int row = wn * 64 + np * 16 + (lane & 7) + ((lane >> 4) & 1) * 8;
                    uint32_t col = ks * 32 + ((lane >> 3) & 1) * 16;
                    uint32_t a = wbase + row * 80 + col;
                    ldsm4(bh[2 * np][0], bh[2 * np][1], bh[2 * np + 1][0], bh[2 * np + 1][1], a);
                }
                #pragma unroll
                for (int mf = 0; mf < 2; mf++) {
                    int rowk = kc * 32 + ks * 16 + ((lane >> 4) & 1) * 8 + (lane & 7);
                    uint32_t col = (wm * 32 + mf * 16 + ((lane >> 3) & 1) * 8) * 2;
                    uint32_t a = sb + G1_A_OF + rowk * 272 + col;
                    uint32_t a0, a1, a2, a3;
                    ldsm4t(a0, a1, a2, a3, a);
                    #pragma unroll
                    for (int nf = 0; nf < 8; nf++)
                        mma_f16(acc[mf][nf], a0, a1, a2, a3, bh[nf][0], bh[nf][1]);
                }
            }
            if (kc + 1 < 8) {
                char* buf = sm1 + G1_W_OF + ((kc + 1) & 1) * G1_W_STAGE;
                #pragma unroll
                for (int i = 0; i < 2; i++) {
                    int s = tid + 256 * i;
                    int o = s >> 2, qq = s & 3;
                    *(uint4*)(buf + o * 80 + qq * 16) = pw[i];
                }
            }
            __syncthreads();
        }

        // write Out fp16 [p][j]; fold b1 into the U branch
        #pragma unroll
        for (int mf = 0; mf < 2; mf++) {
            #pragma unroll
            for (int nf = 0; nf < 8; nf++) {
                size_t r0 = P0 + wm * 32 + mf * 16 + g;
                int col = jt * 128 + wn * 64 + nf * 8 + t2;
                float ba = 0.f, bb = 0.f;
                if (which == 0) { ba = __ldg(b1 + col); bb = __ldg(b1 + col + 1); }
                *(uint32_t*)&Out[r0 * C4 + col] = pack2h(acc[mf][nf][0] + ba, acc[mf][nf][1] + bb);
                *(uint32_t*)&Out[(r0 + 8) * C4 + col] = pack2h(acc[mf][nf][2] + ba, acc[mf][nf][3] + bb);
            }
        }
    }
}

// ==================================================================
// GEMM2 (mma.sync fp16, o-split for tail smoothing):
// grid (NP/128, 2 rolls, 2 o-halves); each block does 4 o-tiles and
// atomicAdds its partial T into g_tT/g_tP (exactly 2 contributors/pixel -> deterministic).
#define G2_A_OF 0
#define G2_B_OF 10240
#define G2_STAGE 20480
__global__ __launch_bounds__(256, 2) void gemm2_mma(const float* __restrict__ b2,
                                                    const float* __restrict__ w3) {
    extern __shared__ __align__(16) char sm2[];
    const int tid = threadIdx.x;
    const int wid = tid >> 5, lane = tid & 31;
    const int wm = wid & 3, wn = wid >> 2;
    const int g = lane >> 2, t2 = (lane & 3) * 2;
    const size_t P0 = (size_t)blockIdx.x * 128;
    const int roll = blockIdx.y;
    const int oh = blockIdx.z;                 // o-half: nt in [oh*4, oh*4+4)
    const __half* Z = (roll ? g_ZP : g_ZT) + P0 * C4;
    float* tOut = roll ? g_tP : g_tT;
    const uint32_t sb = smem_u32(sm2);

    float sAcc[4] = {0.f, 0.f, 0.f, 0.f};

    for (int nt = oh * 4; nt < oh * 4 + 4; nt++) {
        const int o0 = nt * 128;
        const __half* Wh = g_W2h + (size_t)o0 * C4;
        float acc[2][8][4];
        #pragma unroll
        for (int a = 0; a < 2; a++)
            #pragma unroll
            for (int b = 0; b < 8; b++)
                #pragma unroll
                for (int c = 0; c < 4; c++) acc[a][b][c] = 0.f;

        uint4 pa[2], pw[2];
        {
            #pragma unroll
            for (int i = 0; i < 2; i++) {
                int s = tid + 256 * i;
                int p = s >> 2, q = s & 3;
                pa[i] = *(const uint4*)(Z + (size_t)p * C4 + q * 8);
                pw[i] = *(const uint4*)(Wh + (size_t)p * C4 + q * 8);
            }
            char* buf = sm2;
            #pragma unroll
            for (int i = 0; i < 2; i++) {
                int s = tid + 256 * i;
                int p = s >> 2, q = s & 3;
                *(uint4*)(buf + G2_A_OF + p * 80 + q * 16) = pa[i];
                *(uint4*)(buf + G2_B_OF + p * 80 + q * 16) = pw[i];
            }
        }
        __syncthreads();

        for (int kc = 0; kc < 32; kc++) {
            if (kc + 1 < 32) {
                int k0 = (kc + 1) * 32;
                #pragma unroll
                for (int i = 0; i < 2; i++) {
                    int s = tid + 256 * i;
                    int p = s >> 2, q = s & 3;
                    pa[i] = *(const uint4*)(Z + (size_t)p * C4 + k0 + q * 8);
                    pw[i] = *(const uint4*)(Wh + (size_t)p * C4 + k0 + q * 8);
                }
            }
            const uint32_t base = sb + (kc & 1) * G2_STAGE;
            #pragma unroll
            for (int ks = 0; ks < 2; ks++) {
                uint32_t bh[8][2];
                #pragma unroll
                for (int np = 0; np < 4; np++) {
                    int row = wn * 64 + np * 16 + (lane & 7) + ((lane >> 4) & 1) * 8;
                    uint32_t col = ks * 32 + ((lane >> 3) & 1) * 16;
                    uint32_t a = base + G2_B_OF + row * 80 + col;
                    ldsm4(bh[2 * np][0], bh[2 * np][1], bh[2 * np + 1][0], bh[2 * np + 1][1], a);
                }
                #pragma unroll
                for (int mf = 0; mf < 2; mf++) {
                    int row = wm * 32 + mf * 16 + (lane & 7) + ((lane >> 3) & 1) * 8;
                    uint32_t col = ks * 32 + ((lane >> 4) & 1) * 16;
                    uint32_t a = base + G2_A_OF + row * 80 + col;
                    uint32_t a0, a1, a2, a3;
                    ldsm4(a0, a1, a2, a3, a);
                    #pragma unroll
                    for (int nf = 0; nf < 8; nf++)
                        mma_f16(acc[mf][nf], a0, a1, a2, a3, bh[nf][0], bh[nf][1]);
                }
            }
            if (kc + 1 < 32) {
                char* buf = sm2 + ((kc + 1) & 1) * G2_STAGE;
                #pragma unroll
                for (int i = 0; i < 2; i++) {
                    int s = tid + 256 * i;
                    int p = s >> 2, q = s & 3;
                    *(uint4*)(buf + G2_A_OF + p * 80 + q * 16) = pa[i];
                    *(uint4*)(buf + G2_B_OF + p * 80 + q * 16) = pw[i];
                }
            }
            __syncthreads();
        }

        // fold this o-tile into per-pixel scalars
        #pragma unroll
        for (int mf = 0; mf < 2; mf++) {
            #pragma unroll
            for (int nf = 0; nf < 8; nf++) {
                int c0 = o0 + wn * 64 + nf * 8 + t2;
                float b2a = __ldg(b2 + c0), b2b = __ldg(b2 + c0 + 1);
                float w3a = __ldg(w3 + c0), w3b = __ldg(w3 + c0 + 1);
                sAcc[mf * 2 + 0] += fmaxf(acc[mf][nf][0] + b2a, 0.f) * w3a
                                  + fmaxf(acc[mf][nf][1] + b2b, 0.f) * w3b;
                sAcc[mf * 2 + 1] += fmaxf(acc[mf][nf][2] + b2a, 0.f) * w3a
                                  + fmaxf(acc[mf][nf][3] + b2b, 0.f) * w3b;
            }
        }
    }

    // reduce across the 4-lane groups (same rows, different cols)
    #pragma unroll
    for (int i = 0; i < 4; i++) {
        sAcc[i] += __shfl_xor_sync(0xFFFFFFFFu, sAcc[i], 1);
        sAcc[i] += __shfl_xor_sync(0xFFFFFFFFu, sAcc[i], 2);
    }
    __syncthreads();
    float* sRed = (float*)sm2;   // [2][128]
    if ((lane & 3) == 0) {
        #pragma unroll
        for (int i = 0; i < 4; i++) {
            int r = wm * 32 + (i >> 1) * 16 + (i & 1) * 8 + g;
            sRed[wn * 128 + r] = sAcc[i];
        }
    }
    __syncthreads();
    if (tid < 128) atomicAdd(&tOut[P0 + tid], sRed[tid] + sRed[128 + tid]);
}

// ------------------------------------------------------------------
// parallel loss: 40 blocks, double atomics, last-block finalize
#define LOSS_BLOCKS 40
__device__ unsigned int g_lossCnt2;
__global__ void loss_kernel(const float* __restrict__ st_b3, float* __restrict__ out) {
    __shared__ double red[256];
    int t = threadIdx.x;
    float b3 = st_b3[0];
    double s = 0.0;
    for (int i = blockIdx.x * 256 + t; i < NP; i += LOSS_BLOCKS * 256) {
        float tt = g_tT[i] + b3;
        float tp = g_tP[i] + b3;
        s += (double)softplusf(-tt) + (double)softplusf(tp);
    }
    red[t] = s;
    __syncthreads();
    for (int st = 128; st > 0; st >>= 1) { if (t < st) red[t] += red[t + st]; __syncthreads(); }
    if (t == 0) {
        atomicAdd(&g_lossAcc, red[0]);
        __threadfence();
        unsigned int done = atomicAdd(&g_lossCnt2, 1u);
        if (done == LOSS_BLOCKS - 1) {
            g_lossCnt2 = 0u;
            out[LOSS_IDX] = (float)(g_lossAcc / 81920.0);
            out[RATE_IDX] = (float)((double)g_cnt / 16777216.0);
        }
    }
}

// ------------------------------------------------------------------
extern "C" void kernel_launch(void* const* d_in, const int* in_sizes, int n_in,
                              void* d_out, int out_size) {
    const float* feat     = (const float*)d_in[0];
    const float* mlp_w1   = (const float*)d_in[1];
    const float* mlp_w2   = (const float*)d_in[2];
    const float* sp_req_w = (const float*)d_in[3];
    const float* ch_fus_w = (const float*)d_in[4];
    const float* sp_fus_w = (const float*)d_in[5];
    const float* st_w1    = (const float*)d_in[6];
    const float* st_b1    = (const float*)d_in[7];
    const float* st_w2    = (const float*)d_in[8];
    const float* st_b2    = (const float*)d_in[9];
    const float* st_w3    = (const float*)d_in[10];
    const float* st_b3    = (const float*)d_in[11];

    float* out = (float*)d_out;
    float* out_sf = out;
    float* out_sm = out + SM_OFF;

    cudaFuncSetAttribute(gemm1_mma, cudaFuncAttributeMaxDynamicSharedMemorySize, G1_SMEM);
    cudaFuncSetAttribute(gemm2_mma, cudaFuncAttributeMaxDynamicSharedMemorySize, 2 * G2_STAGE);

    front_kernel<<<FRONT_B, 256>>>(st_w1, st_w2, feat);
    chcoef_spatial_kernel<<<CH_B + SPA_B, 256>>>(mlp_w1, mlp_w2, ch_fus_w, sp_req_w);
    spcoef_kernel<<<(4 * HW + 255) / 256, 256>>>(sp_fus_w);
    mask_kernel<<<2048, 256>>>(feat, out_sf, out_sm);

    dim3 g1grid(NP / 128, 2, 2);
    gemm1_mma<<<g1grid, 256, G1_SMEM>>>(st_b1);

    zprep_kernel<<<(HW * (C4 / 8) + 255) / 256, 256>>>();

    dim3 g2grid(NP / 128, 2, 2);
    gemm2_mma<<<g2grid, 256, 2 * G2_STAGE>>>(st_b2, st_w3);

    loss_kernel<<<LOSS_BLOCKS, 256>>>(st_b3, out);
}